// round 6
// baseline (speedup 1.0000x reference)
#include <cuda_runtime.h>

// DCT band decomposition: x[16,3,512,512] f32 -> (low, mid, high) concatenated.
// 8 threads per 8x8 block (one per row). Warp-local smem transposes; band
// masks realized as runtime k-prefix ranges per column (contiguous in zigzag).

namespace {
constexpr int H = 512, W = 512;
constexpr int NPIX = 16 * 3 * H * W;          // 12582912
constexpr int NBLK = 16 * 3 * (H / 8) * (W / 8); // 196608
constexpr int TPB  = 256;                     // 32 blocks per CTA
constexpr int GPC  = TPB / 8;                 // groups per CTA
}

#define A4f 0.3535533905932738f
#define C1f 0.4903926402016152f
#define C2f 0.4619397662556434f
#define C3f 0.4157348061512726f
#define C5f 0.2777851165098011f
#define C6f 0.1913417161825449f
#define C7f 0.0975451610080641f

// Orthonormal 8-point DCT-II matrix (compile-time literals after unroll).
__host__ __device__ constexpr float Dv(int k, int t) {
    constexpr float m[8][8] = {
        { A4f,  A4f,  A4f,  A4f,  A4f,  A4f,  A4f,  A4f},
        { C1f,  C3f,  C5f,  C7f, -C7f, -C5f, -C3f, -C1f},
        { C2f,  C6f, -C6f, -C2f, -C2f, -C6f,  C6f,  C2f},
        { C3f, -C7f, -C1f, -C5f,  C5f,  C1f,  C7f, -C3f},
        { A4f, -A4f, -A4f,  A4f,  A4f, -A4f, -A4f,  A4f},
        { C5f, -C1f,  C7f,  C3f, -C3f, -C7f,  C1f, -C5f},
        { C6f, -C2f,  C2f, -C6f, -C6f,  C2f, -C2f,  C6f},
        { C7f, -C5f,  C3f, -C1f,  C1f, -C3f,  C5f, -C7f}
    };
    return m[k][t];
}

// Fast 8-point forward DCT-II in place.
__device__ __forceinline__ void dct8(float x[8]) {
    const float e0 = x[0] + x[7], e1 = x[1] + x[6], e2 = x[2] + x[5], e3 = x[3] + x[4];
    const float o0 = x[0] - x[7], o1 = x[1] - x[6], o2 = x[2] - x[5], o3 = x[3] - x[4];
    const float f0 = e0 + e3, f1 = e1 + e2;
    const float g0 = e0 - e3, g1 = e1 - e2;
    x[0] = A4f * (f0 + f1);
    x[4] = A4f * (f0 - f1);
    x[2] = fmaf(C2f, g0,  C6f * g1);
    x[6] = fmaf(C6f, g0, -C2f * g1);
    x[1] = fmaf(C1f, o0, fmaf( C3f, o1, fmaf( C5f, o2,  C7f * o3)));
    x[3] = fmaf(C3f, o0, fmaf(-C7f, o1, fmaf(-C1f, o2, -C5f * o3)));
    x[5] = fmaf(C5f, o0, fmaf(-C1f, o1, fmaf( C7f, o2,  C3f * o3)));
    x[7] = fmaf(C7f, o0, fmaf(-C5f, o1, fmaf( C3f, o2, -C1f * o3)));
}

// z[m] = sum_k c[k] * Dv(k, m)   (apply D^T), using m/(7-m) symmetry:
// Dv(k,7-m) = (-1)^k Dv(k,m)  ->  z[m]=se+so, z[7-m]=se-so.
__device__ __forceinline__ void idctvec(const float c[8], float z[8]) {
#pragma unroll
    for (int m = 0; m < 4; m++) {
        float se =            c[0] * Dv(0, m);
        se = fmaf(c[2], Dv(2, m), se);
        se = fmaf(c[4], Dv(4, m), se);
        se = fmaf(c[6], Dv(6, m), se);
        float so =            c[1] * Dv(1, m);
        so = fmaf(c[3], Dv(3, m), so);
        so = fmaf(c[5], Dv(5, m), so);
        so = fmaf(c[7], Dv(7, m), so);
        z[m]     = se + so;
        z[7 - m] = se - so;
    }
}

__global__ void __launch_bounds__(TPB, 5)
dct_decomp_kernel(const float* __restrict__ x,
                  const float* __restrict__ band_scale,
                  float* __restrict__ out)
{
    // Two warp-local transpose buffers (pad 9 -> conflict-free both directions).
    __shared__ float sm[2][GPC][8][9];

    const int tid = threadIdx.x;
    const int gl  = tid >> 3;        // group (block) within CTA
    const int r   = tid & 7;         // row index this thread owns
    const int gid = (blockIdx.x * TPB + tid) >> 3;   // global block id

    const int bw = gid & 63;
    const int bh = (gid >> 6) & 63;
    const int bc = gid >> 12;        // fused batch*chan

    const size_t base = ((size_t)bc * H + (size_t)bh * 8) * W + (size_t)bw * 8;
    const float* src = x + base + (size_t)r * W;

    const float s0 = __ldg(band_scale + 0);
    const float s1 = __ldg(band_scale + 1);
    const float s2 = __ldg(band_scale + 2);

    // ---- Load own row (coalesced: warp covers 4 blocks x 8 rows) ----
    float v[8];
    {
        float4 a = __ldcs(reinterpret_cast<const float4*>(src));
        float4 b = __ldcs(reinterpret_cast<const float4*>(src + 4));
        v[0] = a.x; v[1] = a.y; v[2] = a.z; v[3] = a.w;
        v[4] = b.x; v[5] = b.y; v[6] = b.z; v[7] = b.w;
    }

    // ---- Row DCT: v <- (X D^T)[r][:] ----
    dct8(v);

    // ---- Transpose #1: thread picks up column r ----
#pragma unroll
    for (int l = 0; l < 8; l++) sm[0][gl][r][l] = v[l];
    __syncwarp();
    float c[8];
#pragma unroll
    for (int k = 0; k < 8; k++) c[k] = sm[0][gl][k][r];

    // ---- Column DCT: c[k] = C[k][r] ----
    dct8(c);

    // ---- Band prefix bounds along k for column j=r ----
    // low: k < K0 ; mid: K0 <= k < K1 ; high: k >= K1  (zigzag-exact)
    const int K0 = (r <= 5) ? (6 - r) : 0;
    const int K1 = (r == 0) ? 8 : ((r == 7) ? 1 : 9 - r);

    float cl[8], cp[8];
#pragma unroll
    for (int k = 0; k < 8; k++) {
        cl[k] = (k < K0) ? c[k] : 0.0f;   // low prefix
        cp[k] = (k < K1) ? c[k] : 0.0f;   // low+mid prefix
    }

    // ---- Stage 1 (apply D^T down the column) ----
    float zF[8], z0[8], z1[8];
    idctvec(c,  zF);
    idctvec(cl, z0);
    idctvec(cp, z1);

    float zl[8], zm[8], zh[8];
#pragma unroll
    for (int m = 0; m < 8; m++) {
        zl[m] = z0[m] * s0;
        zm[m] = (z1[m] - z0[m]) * s1;
        zh[m] = (zF[m] - z1[m]) * s2;
    }

    // ---- Per band: transpose #2 then stage 2 (apply D along rows) + store ----
    float* dst = out + base + (size_t)r * W;

    // band 0 (low) -> buffer 1
#pragma unroll
    for (int m = 0; m < 8; m++) sm[1][gl][m][r] = zl[m];
    __syncwarp();
    {
        float z[8];
#pragma unroll
        for (int l = 0; l < 8; l++) z[l] = sm[1][gl][r][l];
        float o[8];
        idctvec(z, o);
        __stcs(reinterpret_cast<float4*>(dst),     make_float4(o[0], o[1], o[2], o[3]));
        __stcs(reinterpret_cast<float4*>(dst + 4), make_float4(o[4], o[5], o[6], o[7]));
    }
    __syncwarp();

    // band 1 (mid) -> buffer 0 (T1 reads are complete: ordered by prior syncwarps)
#pragma unroll
    for (int m = 0; m < 8; m++) sm[0][gl][m][r] = zm[m];
    __syncwarp();
    {
        float z[8];
#pragma unroll
        for (int l = 0; l < 8; l++) z[l] = sm[0][gl][r][l];
        float o[8];
        idctvec(z, o);
        float* d1 = dst + (size_t)NPIX;
        __stcs(reinterpret_cast<float4*>(d1),     make_float4(o[0], o[1], o[2], o[3]));
        __stcs(reinterpret_cast<float4*>(d1 + 4), make_float4(o[4], o[5], o[6], o[7]));
    }
    __syncwarp();

    // band 2 (high) -> buffer 1
#pragma unroll
    for (int m = 0; m < 8; m++) sm[1][gl][m][r] = zh[m];
    __syncwarp();
    {
        float z[8];
#pragma unroll
        for (int l = 0; l < 8; l++) z[l] = sm[1][gl][r][l];
        float o[8];
        idctvec(z, o);
        float* d2 = dst + 2 * (size_t)NPIX;
        __stcs(reinterpret_cast<float4*>(d2),     make_float4(o[0], o[1], o[2], o[3]));
        __stcs(reinterpret_cast<float4*>(d2 + 4), make_float4(o[4], o[5], o[6], o[7]));
    }
}

extern "C" void kernel_launch(void* const* d_in, const int* in_sizes, int n_in,
                              void* d_out, int out_size)
{
    const float* x  = (const float*)d_in[0];
    const float* bs = (const float*)d_in[1];
    float* out = (float*)d_out;

    const int grid = (NBLK * 8) / TPB;   // 6144
    dct_decomp_kernel<<<grid, TPB>>>(x, bs, out);
}

// round 7
// speedup vs baseline: 1.2513x; 1.2513x over previous
#include <cuda_runtime.h>

// DCT band decomposition: x[16,3,512,512] f32 -> (low, mid, high) concatenated.
// One thread per 8x8 block. Butterfly forward DCT; band IDCTs exploit
// m/(7-m) and n/(7-n) cosine symmetry. DCT constants fold to FFMA immediates.
// Loads default-cached (input is L2-resident across graph replays);
// stores evict-first so the 151MB write stream doesn't flush the input.

namespace {
constexpr int H = 512, W = 512;
constexpr int NPIX = 16 * 3 * H * W;             // 12582912
constexpr int NBLK = 16 * 3 * (H / 8) * (W / 8); // 196608
constexpr int TPB  = 128;
}

#define A4f 0.3535533905932738f
#define C1f 0.4903926402016152f
#define C2f 0.4619397662556434f
#define C3f 0.4157348061512726f
#define C5f 0.2777851165098011f
#define C6f 0.1913417161825449f
#define C7f 0.0975451610080641f

// Orthonormal 8-point DCT-II matrix (compile-time literals after unroll).
__host__ __device__ constexpr float Dv(int k, int t) {
    constexpr float m[8][8] = {
        { A4f,  A4f,  A4f,  A4f,  A4f,  A4f,  A4f,  A4f},
        { C1f,  C3f,  C5f,  C7f, -C7f, -C5f, -C3f, -C1f},
        { C2f,  C6f, -C6f, -C2f, -C2f, -C6f,  C6f,  C2f},
        { C3f, -C7f, -C1f, -C5f,  C5f,  C1f,  C7f, -C3f},
        { A4f, -A4f, -A4f,  A4f,  A4f, -A4f, -A4f,  A4f},
        { C5f, -C1f,  C7f,  C3f, -C3f, -C7f,  C1f, -C5f},
        { C6f, -C2f,  C2f, -C6f, -C6f,  C2f, -C2f,  C6f},
        { C7f, -C5f,  C3f, -C1f,  C1f, -C3f,  C5f, -C7f}
    };
    return m[k][t];
}

// Zigzag bands: low = zz<21 <=> k+l<=5 ; mid = 21<=zz<42 <=> 6<=k+l<=8 \ (1,7)
__host__ __device__ constexpr bool in_band(int band, int k, int l) {
    const int s = k + l;
    const bool low = (s <= 5);
    const bool mid = (s >= 6 && s <= 8) && !(k == 1 && l == 7);
    if (band == 0) return low;
    if (band == 1) return mid;
    return !low && !mid;
}
__host__ __device__ constexpr bool col_active(int band, int l) {
    bool a = false;
    for (int k = 0; k < 8; k++) if (in_band(band, k, l)) a = true;
    return a;
}

// Fast 8-point DCT-II (orthonormal) on 8 values in place.
__device__ __forceinline__ void dct8(float x[8]) {
    const float e0 = x[0] + x[7], e1 = x[1] + x[6], e2 = x[2] + x[5], e3 = x[3] + x[4];
    const float o0 = x[0] - x[7], o1 = x[1] - x[6], o2 = x[2] - x[5], o3 = x[3] - x[4];
    const float f0 = e0 + e3, f1 = e1 + e2;
    const float g0 = e0 - e3, g1 = e1 - e2;
    x[0] = A4f * (f0 + f1);
    x[4] = A4f * (f0 - f1);
    x[2] = fmaf(C2f, g0,  C6f * g1);
    x[6] = fmaf(C6f, g0, -C2f * g1);
    x[1] = fmaf(C1f, o0, fmaf( C3f, o1, fmaf( C5f, o2,  C7f * o3)));
    x[3] = fmaf(C3f, o0, fmaf(-C7f, o1, fmaf(-C1f, o2, -C5f * o3)));
    x[5] = fmaf(C5f, o0, fmaf(-C1f, o1, fmaf( C7f, o2,  C3f * o3)));
    x[7] = fmaf(C7f, o0, fmaf(-C5f, o1, fmaf( C3f, o2, -C1f * o3)));
}

// Stage 2 of masked IDCT: o[n] = sum_l y[l]*Dv(l,n) with n/(7-n) symmetry.
template <int BAND>
__device__ __forceinline__ void idct_row_store(const float y[8],
                                               float* __restrict__ dst)
{
    float o[8];
#pragma unroll
    for (int n = 0; n < 4; n++) {
        float E = 0.0f, O = 0.0f;
#pragma unroll
        for (int l = 0; l < 8; l += 2)
            if (col_active(BAND, l)) E = fmaf(y[l], Dv(l, n), E);
#pragma unroll
        for (int l = 1; l < 8; l += 2)
            if (col_active(BAND, l)) O = fmaf(y[l], Dv(l, n), O);
        o[n]     = E + O;
        o[7 - n] = E - O;
    }
    __stcs(reinterpret_cast<float4*>(dst),
           make_float4(o[0], o[1], o[2], o[3]));
    __stcs(reinterpret_cast<float4*>(dst + 4),
           make_float4(o[4], o[5], o[6], o[7]));
}

// Masked inverse DCT of one band, row pairs (m, 7-m):
// Dv(k,7-m) = (-1)^k Dv(k,m), so stage-1 even/odd-k partial sums are shared.
template <int BAND>
__device__ __forceinline__ void band_idct(const float C[8][8], float scale,
                                          float* __restrict__ dst)
{
#pragma unroll
    for (int m = 0; m < 4; m++) {
        float yA[8], yB[8];
#pragma unroll
        for (int l = 0; l < 8; l++) {
            if (col_active(BAND, l)) {
                float se = 0.0f, so = 0.0f;
#pragma unroll
                for (int k = 0; k < 8; k += 2)
                    if (in_band(BAND, k, l)) se = fmaf(C[k][l], Dv(k, m), se);
#pragma unroll
                for (int k = 1; k < 8; k += 2)
                    if (in_band(BAND, k, l)) so = fmaf(C[k][l], Dv(k, m), so);
                yA[l] = (se + so) * scale;   // row m
                yB[l] = (se - so) * scale;   // row 7-m
            } else {
                yA[l] = 0.0f; yB[l] = 0.0f;
            }
        }
        idct_row_store<BAND>(yA, dst + (size_t)m * W);
        idct_row_store<BAND>(yB, dst + (size_t)(7 - m) * W);
    }
}

__global__ void __launch_bounds__(TPB, 6)
dct_decomp_kernel(const float* __restrict__ x,
                  const float* __restrict__ band_scale,
                  float* __restrict__ out)
{
    const int tid = blockIdx.x * TPB + threadIdx.x;   // grid sized exactly
    const int bw = tid & 63;          // block col (W/8 = 64)
    const int bh = (tid >> 6) & 63;   // block row
    const int bc = tid >> 12;         // fused batch*chan

    const size_t base = ((size_t)bc * H + (size_t)bh * 8) * W + (size_t)bw * 8;
    const float* src = x + base;

    const float s0 = __ldg(band_scale + 0);
    const float s1 = __ldg(band_scale + 1);
    const float s2 = __ldg(band_scale + 2);

    // ---- Load 8x8 block (16 independent LDG.128, default caching:
    //      input stays L2-resident across graph replays) ----
    float C[8][8];
#pragma unroll
    for (int r = 0; r < 8; r++) {
        float4 a = __ldg(reinterpret_cast<const float4*>(src + (size_t)r * W));
        float4 b = __ldg(reinterpret_cast<const float4*>(src + (size_t)r * W + 4));
        C[r][0] = a.x; C[r][1] = a.y; C[r][2] = a.z; C[r][3] = a.w;
        C[r][4] = b.x; C[r][5] = b.y; C[r][6] = b.z; C[r][7] = b.w;
    }

    // ---- Forward 2D DCT in place: columns then rows, butterflied ----
#pragma unroll
    for (int t = 0; t < 8; t++) {
        float col[8];
#pragma unroll
        for (int m = 0; m < 8; m++) col[m] = C[m][t];
        dct8(col);
#pragma unroll
        for (int k = 0; k < 8; k++) C[k][t] = col[k];
    }
#pragma unroll
    for (int k = 0; k < 8; k++)
        dct8(C[k]);

    // ---- Three masked inverse DCTs ----
    band_idct<0>(C, s0, out + base);
    band_idct<1>(C, s1, out + (size_t)NPIX + base);
    band_idct<2>(C, s2, out + 2 * (size_t)NPIX + base);
}

extern "C" void kernel_launch(void* const* d_in, const int* in_sizes, int n_in,
                              void* d_out, int out_size)
{
    const float* x  = (const float*)d_in[0];
    const float* bs = (const float*)d_in[1];
    float* out = (float*)d_out;

    const int grid = NBLK / TPB;   // 1536
    dct_decomp_kernel<<<grid, TPB>>>(x, bs, out);
}